// round 14
// baseline (speedup 1.0000x reference)
#include <cuda_runtime.h>
#include <cstdint>

#define EPS_F 1e-5f
#define BDIM 128
#define CDIM 32
#define NA 12
#define NB 12
#define PDIM 8192

#define TPB 256
#define TILE_P 1024        // per block; 4 chunks of 256
#define CHUNK 256
#define NCHUNK (TILE_P / CHUNK)
#define FPAD 13            // feature row stride (odd -> conflict-free gather)
#define ASTR 260           // aggS row stride (odd granules -> conflict-free STS/LDS.128)
#define WSTR 33            // wT row stride (odd -> conflict-free per-lane scalar loads)

// ---------------------------------------------------------------------------
// Packed f32x2 helpers (sm_103a FFMA2 — ptxas never emits this from C++)
// ---------------------------------------------------------------------------
__device__ __forceinline__ unsigned long long pack2(float lo, float hi) {
    unsigned long long r;
    asm("mov.b64 %0, {%1, %2};" : "=l"(r) : "f"(lo), "f"(hi));
    return r;
}
__device__ __forceinline__ void unpack2(unsigned long long v, float& lo, float& hi) {
    asm("mov.b64 {%0, %1}, %2;" : "=f"(lo), "=f"(hi) : "l"(v));
}
__device__ __forceinline__ unsigned long long fma2(unsigned long long a,
                                                   unsigned long long b,
                                                   unsigned long long c) {
    unsigned long long d;
    asm("fma.rn.f32x2 %0, %1, %2, %3;" : "=l"(d) : "l"(a), "l"(b), "l"(c));
    return d;
}

// ---------------------------------------------------------------------------
// R13 structure + register-resident weights broadcast via shfl.
//   Setup once/block; wreg[j] = w[o0+j][lane] loaded ONCE (lane = c).
//   4 chunk-iterations: {prefetch idx -> sync -> shfl-fed gather -> sync ->
//   GEMM with weights from shfl (shuffle unit, zero crossbar)}.
// Phase 2 per c per warp: 8 shfl + 8 pack (ALU) + 1 agg LDS.128 (4 wf) +
//   16 FFMA2. Thread tile 8o x 4pt.
// grid = (8,128); block = 256; ~42KB smem, 3 CTAs/SM.
// ---------------------------------------------------------------------------
__global__ __launch_bounds__(TPB, 3) void feynnet_kernel(
    const float* __restrict__ feat_a, const float* __restrict__ feat_b,
    const int* __restrict__ assign_a, const int* __restrict__ assign_b,
    const float* __restrict__ conv_w,
    const float* __restrict__ g1, const float* __restrict__ b1,
    const float* __restrict__ m1, const float* __restrict__ v1,
    const float* __restrict__ g2, const float* __restrict__ b2,
    const float* __restrict__ m2, const float* __restrict__ v2,
    float* __restrict__ out) {
    __shared__ float s1[CDIM], t1v[CDIM], s2[CDIM], t2v[CDIM];
    __shared__ float faP[CDIM * FPAD];      // 1.7 KB
    __shared__ float fbP[CDIM * FPAD];      // 1.7 KB
    __shared__ float wT[CDIM * WSTR];       // folded W, [c][o], 4.2 KB
    __shared__ float biasS[CDIM];
    __shared__ float aggS[CDIM * ASTR];     // [c][pt in chunk], 33.3 KB

    const int t = threadIdx.x;
    const int lane = t & 31;
    const int wid = t >> 5;
    const int b = blockIdx.y;
    const int ptile = blockIdx.x * TILE_P;

    // ---- Setup (once per block) ----
    if (t < CDIM) {
        float sc1 = g1[t] * rsqrtf(v1[t] + EPS_F);
        s1[t] = sc1;
        t1v[t] = b1[t] - m1[t] * sc1;
        float sc2 = g2[t] * rsqrtf(v2[t] + EPS_F);
        s2[t] = sc2;
        t2v[t] = b2[t] - m2[t] * sc2;
    }
    __syncthreads();
    for (int i = t; i < CDIM * CDIM; i += TPB) {
        int o = i >> 5, c = i & 31;
        wT[c * WSTR + o] = conv_w[i] * s1[c] * s2[o];   // [c][o]
    }
    if (t < CDIM) {
        float s = 0.f;
        #pragma unroll
        for (int c = 0; c < CDIM; c++) s += conv_w[t * CDIM + c] * t1v[c];
        biasS[t] = s * s2[t] + t2v[t];
    }
    for (int i = t; i < CDIM * NA; i += TPB) {          // 384 > TPB: strided
        int c = i / NA, j = i - c * NA;
        faP[c * FPAD + j] = feat_a[b * CDIM * NA + i];
    }
    for (int i = t; i < CDIM * NB; i += TPB) {
        int c = i / NB, j = i - c * NB;
        fbP[c * FPAD + j] = feat_b[b * CDIM * NB + i];
    }
    __syncthreads();

    // Phase-2 thread mapping (constant across chunks)
    const int og = wid >> 1;                 // 0..3  -> o-group of 8 (warp-uniform)
    const int half = wid & 1;                // chunk half (pts 0-127 / 128-255)
    const int o0 = og * 8;
    const int p0 = half * 128 + 4 * lane;    // this thread's 4 points in chunk

    // ---- Weights into registers, ONCE: lane c holds w[o0..o0+7][c] ----
    // Addresses lane*WSTR + o0 + j: WSTR=33 odd -> 32 distinct banks, 1 wf each.
    float wreg[8];
    #pragma unroll
    for (int j = 0; j < 8; j++) wreg[j] = wT[lane * WSTR + o0 + j];

    float biasr[8];
    #pragma unroll
    for (int j = 0; j < 8; j++) biasr[j] = biasS[o0 + j];

    for (int ck = 0; ck < NCHUNK; ck++) {
        const int cbase = ptile + ck * CHUNK;

        // ---- Prefetch this chunk's indices (thread t owns point cbase+t) ----
        const int2 aa = __ldg((const int2*)(assign_a + 2 * (cbase + t)));
        const int2 ab = __ldg((const int2*)(assign_b + 2 * (cbase + t)));

        if (ck) __syncthreads();   // aggS free (previous chunk's GEMM done)

        // ---- Phase 1: gather + max; warp w covers chunk pts [32w, 32w+32) ----
        {
            const int crow = lane * FPAD;    // lane = channel
            float* aggRow = aggS + lane * ASTR + wid * 32;
            #pragma unroll
            for (int j4 = 0; j4 < 8; j4++) {
                float v[4];
                #pragma unroll
                for (int k = 0; k < 4; k++) {
                    const int j = j4 * 4 + k;
                    const int ax = __shfl_sync(0xffffffffu, aa.x, j);
                    const int ay = __shfl_sync(0xffffffffu, aa.y, j);
                    const int bx = __shfl_sync(0xffffffffu, ab.x, j);
                    const int by = __shfl_sync(0xffffffffu, ab.y, j);
                    v[k] = fmaxf(fmaxf(faP[crow + ax], faP[crow + ay]),
                                 fmaxf(fbP[crow + bx], fbP[crow + by]));
                }
                *reinterpret_cast<float4*>(aggRow + j4 * 4) =
                    make_float4(v[0], v[1], v[2], v[3]);
            }
        }
        __syncthreads();

        // ---- Phase 2: thread tile 8 o x 4 pts; weights via shfl ----
        unsigned long long acc[8][2];
        #pragma unroll
        for (int o = 0; o < 8; o++) {
            unsigned long long bp = pack2(biasr[o], biasr[o]);
            acc[o][0] = bp;
            acc[o][1] = bp;
        }

        #pragma unroll
        for (int c = 0; c < CDIM; c++) {
            const ulonglong2 a =
                *reinterpret_cast<const ulonglong2*>(aggS + c * ASTR + p0);

            const float w0 = __shfl_sync(0xffffffffu, wreg[0], c);
            const float w1 = __shfl_sync(0xffffffffu, wreg[1], c);
            const float w2 = __shfl_sync(0xffffffffu, wreg[2], c);
            const float w3 = __shfl_sync(0xffffffffu, wreg[3], c);
            const float w4 = __shfl_sync(0xffffffffu, wreg[4], c);
            const float w5 = __shfl_sync(0xffffffffu, wreg[5], c);
            const float w6 = __shfl_sync(0xffffffffu, wreg[6], c);
            const float w7 = __shfl_sync(0xffffffffu, wreg[7], c);

            unsigned long long W;
            W = pack2(w0, w0);
            acc[0][0] = fma2(W, a.x, acc[0][0]);
            acc[0][1] = fma2(W, a.y, acc[0][1]);
            W = pack2(w1, w1);
            acc[1][0] = fma2(W, a.x, acc[1][0]);
            acc[1][1] = fma2(W, a.y, acc[1][1]);
            W = pack2(w2, w2);
            acc[2][0] = fma2(W, a.x, acc[2][0]);
            acc[2][1] = fma2(W, a.y, acc[2][1]);
            W = pack2(w3, w3);
            acc[3][0] = fma2(W, a.x, acc[3][0]);
            acc[3][1] = fma2(W, a.y, acc[3][1]);
            W = pack2(w4, w4);
            acc[4][0] = fma2(W, a.x, acc[4][0]);
            acc[4][1] = fma2(W, a.y, acc[4][1]);
            W = pack2(w5, w5);
            acc[5][0] = fma2(W, a.x, acc[5][0]);
            acc[5][1] = fma2(W, a.y, acc[5][1]);
            W = pack2(w6, w6);
            acc[6][0] = fma2(W, a.x, acc[6][0]);
            acc[6][1] = fma2(W, a.y, acc[6][1]);
            W = pack2(w7, w7);
            acc[7][0] = fma2(W, a.x, acc[7][0]);
            acc[7][1] = fma2(W, a.y, acc[7][1]);
        }

        // ---- Epilogue: relu + coalesced float4 stores ----
        float* ob = out + (size_t)b * CDIM * PDIM + cbase + p0;
        #pragma unroll
        for (int o = 0; o < 8; o++) {
            float x0, x1, x2, x3;
            unpack2(acc[o][0], x0, x1);
            unpack2(acc[o][1], x2, x3);
            *reinterpret_cast<float4*>(ob + (size_t)(o0 + o) * PDIM) =
                make_float4(fmaxf(x0, 0.f), fmaxf(x1, 0.f),
                            fmaxf(x2, 0.f), fmaxf(x3, 0.f));
        }
    }
}

// ---------------------------------------------------------------------------
// Launch
// ---------------------------------------------------------------------------
extern "C" void kernel_launch(void* const* d_in, const int* in_sizes, int n_in,
                              void* d_out, int out_size) {
    const float* feat_a = (const float*)d_in[0];
    const float* feat_b = (const float*)d_in[1];
    const int* assign_a = (const int*)d_in[2];
    const int* assign_b = (const int*)d_in[3];
    const float* bn1_gamma = (const float*)d_in[4];
    const float* bn1_beta = (const float*)d_in[5];
    const float* bn1_mean = (const float*)d_in[6];
    const float* bn1_var = (const float*)d_in[7];
    const float* conv_w = (const float*)d_in[8];
    const float* bn2_gamma = (const float*)d_in[9];
    const float* bn2_beta = (const float*)d_in[10];
    const float* bn2_mean = (const float*)d_in[11];
    const float* bn2_var = (const float*)d_in[12];
    float* out = (float*)d_out;

    dim3 grid(PDIM / TILE_P, BDIM);
    feynnet_kernel<<<grid, TPB>>>(feat_a, feat_b, assign_a, assign_b,
                                  conv_w,
                                  bn1_gamma, bn1_beta, bn1_mean, bn1_var,
                                  bn2_gamma, bn2_beta, bn2_mean, bn2_var,
                                  out);
}

// round 15
// speedup vs baseline: 1.1982x; 1.1982x over previous
#include <cuda_runtime.h>
#include <cstdint>

#define EPS_F 1e-5f
#define BDIM 128
#define CDIM 32
#define NA 12
#define NB 12
#define PDIM 8192

#define TPB 128
#define TILE_P 1024        // per block; 4 chunks of 256
#define CHUNK 256
#define NCHUNK (TILE_P / CHUNK)
#define FPAD 13            // feature row stride (odd -> conflict-free gather)
#define ASTR 260           // aggS row stride (odd 16B-granules -> conflict-free STS/LDS.128)
#define WSTR 36            // wT row stride (16B-aligned rows for uniform LDS.128)

// ---------------------------------------------------------------------------
// Packed f32x2 helpers (sm_103a FFMA2 — ptxas never emits this from C++)
// ---------------------------------------------------------------------------
__device__ __forceinline__ unsigned long long pack2(float lo, float hi) {
    unsigned long long r;
    asm("mov.b64 %0, {%1, %2};" : "=l"(r) : "f"(lo), "f"(hi));
    return r;
}
__device__ __forceinline__ void unpack2(unsigned long long v, float& lo, float& hi) {
    asm("mov.b64 {%0, %1}, %2;" : "=f"(lo), "=f"(hi) : "l"(v));
}
__device__ __forceinline__ unsigned long long fma2(unsigned long long a,
                                                   unsigned long long b,
                                                   unsigned long long c) {
    unsigned long long d;
    asm("fma.rn.f32x2 %0, %1, %2, %3;" : "=l"(d) : "l"(a), "l"(b), "l"(c));
    return d;
}

// ---------------------------------------------------------------------------
// TPB=128, 4 warps. Per block: setup once, 4 chunks of 256 points.
// Gather (lane = channel, stride-13 rows): indices nibble-packed — one uint32
//   holds BOTH points of the owning thread (8 indices x 4 bits) -> 1 shfl per
//   2 points (was 4 shfl/pt).
// GEMM: warp = 8 o x FULL 256-pt chunk (8 pts/thread) -> weights 4 wf/pt,
//   agg 4 wf/pt (calibrated model: weights=1024/Tp, agg=32/To).
//   Weights via 2 warp-uniform LDS.128 per c (proven R13 path, no shfl).
// grid = (8,128); block = 128; ~43.5KB smem, 4 CTAs/SM.
// ---------------------------------------------------------------------------
__global__ __launch_bounds__(TPB, 4) void feynnet_kernel(
    const float* __restrict__ feat_a, const float* __restrict__ feat_b,
    const int* __restrict__ assign_a, const int* __restrict__ assign_b,
    const float* __restrict__ conv_w,
    const float* __restrict__ g1, const float* __restrict__ b1,
    const float* __restrict__ m1, const float* __restrict__ v1,
    const float* __restrict__ g2, const float* __restrict__ b2,
    const float* __restrict__ m2, const float* __restrict__ v2,
    float* __restrict__ out) {
    __shared__ float s1[CDIM], t1v[CDIM], s2[CDIM], t2v[CDIM];
    __shared__ float faP[CDIM * FPAD];      // 1.7 KB
    __shared__ float fbP[CDIM * FPAD];      // 1.7 KB
    __shared__ float wT[CDIM * WSTR];       // folded W, [c][o], 4.6 KB
    __shared__ float biasS[CDIM];
    __shared__ float aggS[CDIM * ASTR];     // [c][pt in chunk], 33.3 KB

    const int t = threadIdx.x;
    const int lane = t & 31;
    const int wid = t >> 5;                  // 0..3
    const int b = blockIdx.y;
    const int ptile = blockIdx.x * TILE_P;

    // ---- Setup (once per block) ----
    if (t < CDIM) {
        float sc1 = g1[t] * rsqrtf(v1[t] + EPS_F);
        s1[t] = sc1;
        t1v[t] = b1[t] - m1[t] * sc1;
        float sc2 = g2[t] * rsqrtf(v2[t] + EPS_F);
        s2[t] = sc2;
        t2v[t] = b2[t] - m2[t] * sc2;
    }
    __syncthreads();
    for (int i = t; i < CDIM * CDIM; i += TPB) {
        int o = i >> 5, c = i & 31;
        wT[c * WSTR + o] = conv_w[i] * s1[c] * s2[o];   // [c][o]
    }
    if (t < CDIM) {
        float s = 0.f;
        #pragma unroll
        for (int c = 0; c < CDIM; c++) s += conv_w[t * CDIM + c] * t1v[c];
        biasS[t] = s * s2[t] + t2v[t];
    }
    for (int i = t; i < CDIM * NA; i += TPB) {          // 384 > TPB: strided
        int c = i / NA, j = i - c * NA;
        faP[c * FPAD + j] = feat_a[b * CDIM * NA + i];
    }
    for (int i = t; i < CDIM * NB; i += TPB) {
        int c = i / NB, j = i - c * NB;
        fbP[c * FPAD + j] = feat_b[b * CDIM * NB + i];
    }
    __syncthreads();

    // GEMM mapping: warp = o-group of 8, all 256 points (8/thread)
    const int o0 = wid * 8;
    float biasr[8];
    #pragma unroll
    for (int j = 0; j < 8; j++) biasr[j] = biasS[o0 + j];

    for (int ck = 0; ck < NCHUNK; ck++) {
        const int cbase = ptile + ck * CHUNK;

        // ---- Prefetch + nibble-pack indices: thread owns pts 2t, 2t+1 ----
        // qa = assign_a rows for both points (int4 = 4 indices), same for B.
        uint32_t pk;
        {
            const int4 qa = __ldg((const int4*)(assign_a + 4 * (cbase / 2 + t)));
            const int4 qb = __ldg((const int4*)(assign_b + 4 * (cbase / 2 + t)));
            pk = (uint32_t)qa.x | ((uint32_t)qa.y << 4) |
                 ((uint32_t)qb.x << 8) | ((uint32_t)qb.y << 12) |
                 ((uint32_t)qa.z << 16) | ((uint32_t)qa.w << 20) |
                 ((uint32_t)qb.z << 24) | ((uint32_t)qb.w << 28);
        }

        if (ck) __syncthreads();   // aggS free (previous chunk's GEMM done)

        // ---- Gather + max; warp w covers chunk pts [64w, 64w+64) ----
        {
            const int crow = lane * FPAD;    // lane = channel
            float* aggRow = aggS + lane * ASTR + wid * 64;
            #pragma unroll
            for (int j2 = 0; j2 < 32; j2 += 2) {
                const uint32_t pA = __shfl_sync(0xffffffffu, pk, j2);
                const uint32_t pB = __shfl_sync(0xffffffffu, pk, j2 + 1);
                float v0 = fmaxf(
                    fmaxf(faP[crow + (pA & 15)], faP[crow + ((pA >> 4) & 15)]),
                    fmaxf(fbP[crow + ((pA >> 8) & 15)], fbP[crow + ((pA >> 12) & 15)]));
                float v1 = fmaxf(
                    fmaxf(faP[crow + ((pA >> 16) & 15)], faP[crow + ((pA >> 20) & 15)]),
                    fmaxf(fbP[crow + ((pA >> 24) & 15)], fbP[crow + (pA >> 28)]));
                float v2 = fmaxf(
                    fmaxf(faP[crow + (pB & 15)], faP[crow + ((pB >> 4) & 15)]),
                    fmaxf(fbP[crow + ((pB >> 8) & 15)], fbP[crow + ((pB >> 12) & 15)]));
                float v3 = fmaxf(
                    fmaxf(faP[crow + ((pB >> 16) & 15)], faP[crow + ((pB >> 20) & 15)]),
                    fmaxf(fbP[crow + ((pB >> 24) & 15)], fbP[crow + (pB >> 28)]));
                *reinterpret_cast<float4*>(aggRow + 2 * j2) =
                    make_float4(v0, v1, v2, v3);
            }
        }
        __syncthreads();

        // ---- GEMM: thread tile 8 o x 8 pts (4l..4l+3, 128+4l..128+4l+3) ----
        unsigned long long acc[8][4];
        #pragma unroll
        for (int o = 0; o < 8; o++) {
            unsigned long long bp = pack2(biasr[o], biasr[o]);
            acc[o][0] = bp; acc[o][1] = bp; acc[o][2] = bp; acc[o][3] = bp;
        }

        #pragma unroll
        for (int c = 0; c < CDIM; c++) {
            const float4 wa = *reinterpret_cast<const float4*>(wT + c * WSTR + o0);
            const float4 wb = *reinterpret_cast<const float4*>(wT + c * WSTR + o0 + 4);
            const float* arow = aggS + c * ASTR + 4 * lane;
            const ulonglong2 a0 = *reinterpret_cast<const ulonglong2*>(arow);
            const ulonglong2 a1 = *reinterpret_cast<const ulonglong2*>(arow + 128);

            unsigned long long W;
            W = pack2(wa.x, wa.x);
            acc[0][0] = fma2(W, a0.x, acc[0][0]);
            acc[0][1] = fma2(W, a0.y, acc[0][1]);
            acc[0][2] = fma2(W, a1.x, acc[0][2]);
            acc[0][3] = fma2(W, a1.y, acc[0][3]);
            W = pack2(wa.y, wa.y);
            acc[1][0] = fma2(W, a0.x, acc[1][0]);
            acc[1][1] = fma2(W, a0.y, acc[1][1]);
            acc[1][2] = fma2(W, a1.x, acc[1][2]);
            acc[1][3] = fma2(W, a1.y, acc[1][3]);
            W = pack2(wa.z, wa.z);
            acc[2][0] = fma2(W, a0.x, acc[2][0]);
            acc[2][1] = fma2(W, a0.y, acc[2][1]);
            acc[2][2] = fma2(W, a1.x, acc[2][2]);
            acc[2][3] = fma2(W, a1.y, acc[2][3]);
            W = pack2(wa.w, wa.w);
            acc[3][0] = fma2(W, a0.x, acc[3][0]);
            acc[3][1] = fma2(W, a0.y, acc[3][1]);
            acc[3][2] = fma2(W, a1.x, acc[3][2]);
            acc[3][3] = fma2(W, a1.y, acc[3][3]);
            W = pack2(wb.x, wb.x);
            acc[4][0] = fma2(W, a0.x, acc[4][0]);
            acc[4][1] = fma2(W, a0.y, acc[4][1]);
            acc[4][2] = fma2(W, a1.x, acc[4][2]);
            acc[4][3] = fma2(W, a1.y, acc[4][3]);
            W = pack2(wb.y, wb.y);
            acc[5][0] = fma2(W, a0.x, acc[5][0]);
            acc[5][1] = fma2(W, a0.y, acc[5][1]);
            acc[5][2] = fma2(W, a1.x, acc[5][2]);
            acc[5][3] = fma2(W, a1.y, acc[5][3]);
            W = pack2(wb.z, wb.z);
            acc[6][0] = fma2(W, a0.x, acc[6][0]);
            acc[6][1] = fma2(W, a0.y, acc[6][1]);
            acc[6][2] = fma2(W, a1.x, acc[6][2]);
            acc[6][3] = fma2(W, a1.y, acc[6][3]);
            W = pack2(wb.w, wb.w);
            acc[7][0] = fma2(W, a0.x, acc[7][0]);
            acc[7][1] = fma2(W, a0.y, acc[7][1]);
            acc[7][2] = fma2(W, a1.x, acc[7][2]);
            acc[7][3] = fma2(W, a1.y, acc[7][3]);
        }

        // ---- Epilogue: relu + coalesced float4 stores ----
        float* ob = out + (size_t)b * CDIM * PDIM + cbase + 4 * lane;
        #pragma unroll
        for (int o = 0; o < 8; o++) {
            float* rowp = ob + (size_t)(o0 + o) * PDIM;
            float x0, x1, x2, x3;
            unpack2(acc[o][0], x0, x1);
            unpack2(acc[o][1], x2, x3);
            *reinterpret_cast<float4*>(rowp) =
                make_float4(fmaxf(x0, 0.f), fmaxf(x1, 0.f),
                            fmaxf(x2, 0.f), fmaxf(x3, 0.f));
            unpack2(acc[o][2], x0, x1);
            unpack2(acc[o][3], x2, x3);
            *reinterpret_cast<float4*>(rowp + 128) =
                make_float4(fmaxf(x0, 0.f), fmaxf(x1, 0.f),
                            fmaxf(x2, 0.f), fmaxf(x3, 0.f));
        }
    }
}

// ---------------------------------------------------------------------------
// Launch
// ---------------------------------------------------------------------------
extern "C" void kernel_launch(void* const* d_in, const int* in_sizes, int n_in,
                              void* d_out, int out_size) {
    const float* feat_a = (const float*)d_in[0];
    const float* feat_b = (const float*)d_in[1];
    const int* assign_a = (const int*)d_in[2];
    const int* assign_b = (const int*)d_in[3];
    const float* bn1_gamma = (const float*)d_in[4];
    const float* bn1_beta = (const float*)d_in[5];
    const float* bn1_mean = (const float*)d_in[6];
    const float* bn1_var = (const float*)d_in[7];
    const float* conv_w = (const float*)d_in[8];
    const float* bn2_gamma = (const float*)d_in[9];
    const float* bn2_beta = (const float*)d_in[10];
    const float* bn2_mean = (const float*)d_in[11];
    const float* bn2_var = (const float*)d_in[12];
    float* out = (float*)d_out;

    dim3 grid(PDIM / TILE_P, BDIM);
    feynnet_kernel<<<grid, TPB>>>(feat_a, feat_b, assign_a, assign_b,
                                  conv_w,
                                  bn1_gamma, bn1_beta, bn1_mean, bn1_var,
                                  bn2_gamma, bn2_beta, bn2_mean, bn2_var,
                                  out);
}

// round 16
// speedup vs baseline: 1.2991x; 1.0842x over previous
#include <cuda_runtime.h>
#include <cstdint>

#define EPS_F 1e-5f
#define BDIM 128
#define CDIM 32
#define NA 12
#define NB 12
#define PDIM 8192

#define TPB 128
#define TILE_P 1024        // per block; 4 chunks of 256
#define CHUNK 256
#define NCHUNK (TILE_P / CHUNK)
#define FPAD 13            // feature row stride (odd -> conflict-free gather)
#define ASTR 260           // aggS row stride (odd 16B-granules -> conflict-free STS.128)
#define WSTR 33            // wS row stride [o][c]

// ---------------------------------------------------------------------------
// tf32 helpers (base-target ISA; verified in R12: rel_err 4.2e-7)
// ---------------------------------------------------------------------------
__device__ __forceinline__ uint32_t to_tf32(float x) {
    uint32_t r;
    asm("cvt.rna.tf32.f32 %0, %1;" : "=r"(r) : "f"(x));
    return r;
}
__device__ __forceinline__ void mma_tf32(float& d0, float& d1, float& d2, float& d3,
                                         uint32_t a0, uint32_t a1, uint32_t a2, uint32_t a3,
                                         uint32_t b0, uint32_t b1) {
    asm volatile(
        "mma.sync.aligned.m16n8k8.row.col.f32.tf32.tf32.f32 "
        "{%0,%1,%2,%3}, {%4,%5,%6,%7}, {%8,%9}, {%0,%1,%2,%3};"
        : "+f"(d0), "+f"(d1), "+f"(d2), "+f"(d3)
        : "r"(a0), "r"(a1), "r"(a2), "r"(a3), "r"(b0), "r"(b1));
}

// ---------------------------------------------------------------------------
// Hybrid: R15 chunked structure + R12 tf32 mma GEMM.
//   Setup once/block; W tf32 hi/lo fragments resident in registers.
//   4 chunks: {prefetch nibble-packed idx -> sync -> shfl-fed gather ->
//   sync -> mma phase-2 (warp = 32 o x 64 pts)}.
// 3-term split: D = Whi*Bhi + Wlo*Bhi + Whi*Blo (dropped term ~2^-22).
// grid = (8,128); block = 128; ~41KB smem, 4 CTAs/SM.
// ---------------------------------------------------------------------------
__global__ __launch_bounds__(TPB, 4) void feynnet_kernel(
    const float* __restrict__ feat_a, const float* __restrict__ feat_b,
    const int* __restrict__ assign_a, const int* __restrict__ assign_b,
    const float* __restrict__ conv_w,
    const float* __restrict__ g1, const float* __restrict__ b1,
    const float* __restrict__ m1, const float* __restrict__ v1,
    const float* __restrict__ g2, const float* __restrict__ b2,
    const float* __restrict__ m2, const float* __restrict__ v2,
    float* __restrict__ out) {
    __shared__ float s1[CDIM], t1v[CDIM], s2[CDIM], t2v[CDIM];
    __shared__ float faP[CDIM * FPAD];      // 1.7 KB
    __shared__ float fbP[CDIM * FPAD];      // 1.7 KB
    __shared__ float wS[CDIM * WSTR];       // folded W, [o][c], 4.2 KB
    __shared__ float biasS[CDIM];
    __shared__ float aggS[CDIM * ASTR];     // [c][pt in chunk], 33.3 KB

    const int t = threadIdx.x;
    const int lane = t & 31;
    const int wid = t >> 5;                  // 0..3
    const int g = lane >> 2;                 // 0..7
    const int tg = lane & 3;                 // 0..3
    const int b = blockIdx.y;
    const int ptile = blockIdx.x * TILE_P;

    // ---- Setup (once per block) ----
    if (t < CDIM) {
        float sc1 = g1[t] * rsqrtf(v1[t] + EPS_F);
        s1[t] = sc1;
        t1v[t] = b1[t] - m1[t] * sc1;
        float sc2 = g2[t] * rsqrtf(v2[t] + EPS_F);
        s2[t] = sc2;
        t2v[t] = b2[t] - m2[t] * sc2;
    }
    __syncthreads();
    for (int i = t; i < CDIM * CDIM; i += TPB) {
        int o = i >> 5, c = i & 31;
        wS[o * WSTR + c] = conv_w[i] * s1[c] * s2[o];   // [o][c]
    }
    if (t < CDIM) {
        float s = 0.f;
        #pragma unroll
        for (int c = 0; c < CDIM; c++) s += conv_w[t * CDIM + c] * t1v[c];
        biasS[t] = s * s2[t] + t2v[t];
    }
    for (int i = t; i < CDIM * NA; i += TPB) {          // 384 > TPB: strided
        int c = i / NA, j = i - c * NA;
        faP[c * FPAD + j] = feat_a[b * CDIM * NA + i];
    }
    for (int i = t; i < CDIM * NB; i += TPB) {
        int c = i / NB, j = i - c * NB;
        fbP[c * FPAD + j] = feat_b[b * CDIM * NB + i];
    }
    __syncthreads();

    // ---- A fragments (W tf32 hi/lo), resident for whole kernel (R12 layout) ----
    // a0=(row g, col tg) a1=(g+8,tg) a2=(g,tg+4) a3=(g+8,tg+4)
    uint32_t aH[2][4][4], aL[2][4][4];
    #pragma unroll
    for (int mt = 0; mt < 2; mt++) {
        #pragma unroll
        for (int kt = 0; kt < 4; kt++) {
            int r0 = (mt * 16 + g) * WSTR, r1 = (mt * 16 + g + 8) * WSTR;
            int c0 = kt * 8 + tg;
            float w0 = wS[r0 + c0];
            float w1 = wS[r1 + c0];
            float w2 = wS[r0 + c0 + 4];
            float w3 = wS[r1 + c0 + 4];
            aH[mt][kt][0] = to_tf32(w0);
            aH[mt][kt][1] = to_tf32(w1);
            aH[mt][kt][2] = to_tf32(w2);
            aH[mt][kt][3] = to_tf32(w3);
            aL[mt][kt][0] = to_tf32(w0 - __uint_as_float(aH[mt][kt][0]));
            aL[mt][kt][1] = to_tf32(w1 - __uint_as_float(aH[mt][kt][1]));
            aL[mt][kt][2] = to_tf32(w2 - __uint_as_float(aH[mt][kt][2]));
            aL[mt][kt][3] = to_tf32(w3 - __uint_as_float(aH[mt][kt][3]));
        }
    }
    float bias_r[2][2];
    bias_r[0][0] = biasS[g];
    bias_r[0][1] = biasS[g + 8];
    bias_r[1][0] = biasS[16 + g];
    bias_r[1][1] = biasS[24 + g];

    for (int ck = 0; ck < NCHUNK; ck++) {
        const int cbase = ptile + ck * CHUNK;

        // ---- Prefetch + nibble-pack indices (thread owns pts 2t, 2t+1) ----
        uint32_t pk;
        {
            const int4 qa = __ldg((const int4*)(assign_a + 4 * (cbase / 2 + t)));
            const int4 qb = __ldg((const int4*)(assign_b + 4 * (cbase / 2 + t)));
            pk = (uint32_t)qa.x | ((uint32_t)qa.y << 4) |
                 ((uint32_t)qb.x << 8) | ((uint32_t)qb.y << 12) |
                 ((uint32_t)qa.z << 16) | ((uint32_t)qa.w << 20) |
                 ((uint32_t)qb.z << 24) | ((uint32_t)qb.w << 28);
        }

        if (ck) __syncthreads();   // aggS free (previous chunk's GEMM done)

        // ---- Gather + max; warp w covers chunk pts [64w, 64w+64) (R15) ----
        {
            const int crow = lane * FPAD;    // lane = channel
            float* aggRow = aggS + lane * ASTR + wid * 64;
            #pragma unroll
            for (int j2 = 0; j2 < 32; j2 += 2) {
                const uint32_t pA = __shfl_sync(0xffffffffu, pk, j2);
                const uint32_t pB = __shfl_sync(0xffffffffu, pk, j2 + 1);
                float v0 = fmaxf(
                    fmaxf(faP[crow + (pA & 15)], faP[crow + ((pA >> 4) & 15)]),
                    fmaxf(fbP[crow + ((pA >> 8) & 15)], fbP[crow + ((pA >> 12) & 15)]));
                float v1 = fmaxf(
                    fmaxf(faP[crow + ((pA >> 16) & 15)], faP[crow + ((pA >> 20) & 15)]),
                    fmaxf(fbP[crow + ((pA >> 24) & 15)], fbP[crow + (pA >> 28)]));
                float v2 = fmaxf(
                    fmaxf(faP[crow + (pB & 15)], faP[crow + ((pB >> 4) & 15)]),
                    fmaxf(fbP[crow + ((pB >> 8) & 15)], fbP[crow + ((pB >> 12) & 15)]));
                float v3 = fmaxf(
                    fmaxf(faP[crow + ((pB >> 16) & 15)], faP[crow + ((pB >> 20) & 15)]),
                    fmaxf(fbP[crow + ((pB >> 24) & 15)], fbP[crow + (pB >> 28)]));
                *reinterpret_cast<float4*>(aggRow + 2 * j2) =
                    make_float4(v0, v1, v2, v3);
            }
        }
        __syncthreads();

        // ---- Phase 2: mma; warp = 32 o x 64 pts, 8 n-tiles (R12 layout) ----
        const int wpt0 = wid * 64;
        #pragma unroll
        for (int nt = 0; nt < 8; nt++) {
            const int ptb = wpt0 + nt * 8 + g;
            uint32_t bh[4][2], bl[4][2];
            #pragma unroll
            for (int kt = 0; kt < 4; kt++) {
                float f0 = aggS[(kt * 8 + tg) * ASTR + ptb];
                float f1 = aggS[(kt * 8 + tg + 4) * ASTR + ptb];
                bh[kt][0] = to_tf32(f0);
                bh[kt][1] = to_tf32(f1);
                bl[kt][0] = to_tf32(f0 - __uint_as_float(bh[kt][0]));
                bl[kt][1] = to_tf32(f1 - __uint_as_float(bh[kt][1]));
            }

            float d[2][4] = {{0.f, 0.f, 0.f, 0.f}, {0.f, 0.f, 0.f, 0.f}};
            #pragma unroll
            for (int kt = 0; kt < 4; kt++) {
                #pragma unroll
                for (int mt = 0; mt < 2; mt++) {
                    mma_tf32(d[mt][0], d[mt][1], d[mt][2], d[mt][3],
                             aH[mt][kt][0], aH[mt][kt][1], aH[mt][kt][2], aH[mt][kt][3],
                             bh[kt][0], bh[kt][1]);
                    mma_tf32(d[mt][0], d[mt][1], d[mt][2], d[mt][3],
                             aL[mt][kt][0], aL[mt][kt][1], aL[mt][kt][2], aL[mt][kt][3],
                             bh[kt][0], bh[kt][1]);
                    mma_tf32(d[mt][0], d[mt][1], d[mt][2], d[mt][3],
                             aH[mt][kt][0], aH[mt][kt][1], aH[mt][kt][2], aH[mt][kt][3],
                             bl[kt][0], bl[kt][1]);
                }
            }

            // Epilogue: rows o = mt*16+g (+8), cols pt = nt*8 + tg*2 (+1)
            const size_t pcol = (size_t)cbase + wpt0 + nt * 8 + tg * 2;
            float* ob = out + (size_t)b * CDIM * PDIM + pcol;
            #pragma unroll
            for (int mt = 0; mt < 2; mt++) {
                float x0 = fmaxf(d[mt][0] + bias_r[mt][0], 0.f);
                float x1 = fmaxf(d[mt][1] + bias_r[mt][0], 0.f);
                float x2 = fmaxf(d[mt][2] + bias_r[mt][1], 0.f);
                float x3 = fmaxf(d[mt][3] + bias_r[mt][1], 0.f);
                *reinterpret_cast<float2*>(ob + (size_t)(mt * 16 + g) * PDIM) =
                    make_float2(x0, x1);
                *reinterpret_cast<float2*>(ob + (size_t)(mt * 16 + g + 8) * PDIM) =
                    make_float2(x2, x3);
            }
        }
    }
}

// ---------------------------------------------------------------------------
// Launch
// ---------------------------------------------------------------------------
extern "C" void kernel_launch(void* const* d_in, const int* in_sizes, int n_in,
                              void* d_out, int out_size) {
    const float* feat_a = (const float*)d_in[0];
    const float* feat_b = (const float*)d_in[1];
    const int* assign_a = (const int*)d_in[2];
    const int* assign_b = (const int*)d_in[3];
    const float* bn1_gamma = (const float*)d_in[4];
    const float* bn1_beta = (const float*)d_in[5];
    const float* bn1_mean = (const float*)d_in[6];
    const float* bn1_var = (const float*)d_in[7];
    const float* conv_w = (const float*)d_in[8];
    const float* bn2_gamma = (const float*)d_in[9];
    const float* bn2_beta = (const float*)d_in[10];
    const float* bn2_mean = (const float*)d_in[11];
    const float* bn2_var = (const float*)d_in[12];
    float* out = (float*)d_out;

    dim3 grid(PDIM / TILE_P, BDIM);
    feynnet_kernel<<<grid, TPB>>>(feat_a, feat_b, assign_a, assign_b,
                                  conv_w,
                                  bn1_gamma, bn1_beta, bn1_mean, bn1_var,
                                  bn2_gamma, bn2_beta, bn2_mean, bn2_var,
                                  out);
}

// round 17
// speedup vs baseline: 1.5271x; 1.1755x over previous
#include <cuda_runtime.h>
#include <cstdint>

#define EPS_F 1e-5f
#define BDIM 128
#define CDIM 32
#define NA 12
#define NB 12
#define PDIM 8192

#define TPB 128
#define TILE_P 1024        // per block; 4 chunks of 256
#define CHUNK 256
#define NCHUNK (TILE_P / CHUNK)
#define FPAD 13            // feature row stride (conflict-free precompute reads)
#define NPAIR 144          // 12*12 possible (i0,i1) pairs
#define PMS 33             // pm row stride [pair][c] (odd -> conflict-free)
#define WSTR 33            // wS row stride [o][c]

// ---------------------------------------------------------------------------
// tf32 helpers (base-target ISA; verified R12/R16: rel_err 4.2e-7)
// ---------------------------------------------------------------------------
__device__ __forceinline__ uint32_t to_tf32(float x) {
    uint32_t r;
    asm("cvt.rna.tf32.f32 %0, %1;" : "=r"(r) : "f"(x));
    return r;
}
__device__ __forceinline__ void mma_tf32(float& d0, float& d1, float& d2, float& d3,
                                         uint32_t a0, uint32_t a1, uint32_t a2, uint32_t a3,
                                         uint32_t b0, uint32_t b1) {
    asm volatile(
        "mma.sync.aligned.m16n8k8.row.col.f32.tf32.tf32.f32 "
        "{%0,%1,%2,%3}, {%4,%5,%6,%7}, {%8,%9}, {%0,%1,%2,%3};"
        : "+f"(d0), "+f"(d1), "+f"(d2), "+f"(d3)
        : "r"(a0), "r"(a1), "r"(a2), "r"(a3), "r"(b0), "r"(b1));
}

// ---------------------------------------------------------------------------
// R16 mma structure + pair-max precomputation (gather loop deleted).
//   Setup once/block: fold W -> A tf32 hi/lo frags in registers; build
//   pmA/pmB[pair][c] = max over the pair's two constituents (144 pairs).
//   Per chunk: {compute+store packed pair ids -> sync -> mma phase
//   where B-frag value = max(pmA[pairA][c], pmB[pairB][c]) fused inline}.
// 3-term split: D = Whi*Bhi + Wlo*Bhi + Whi*Blo (dropped term ~2^-22).
// grid = (8,128); block = 128; 46.1KB static smem, 4 CTAs/SM.
// ---------------------------------------------------------------------------
__global__ __launch_bounds__(TPB, 4) void feynnet_kernel(
    const float* __restrict__ feat_a, const float* __restrict__ feat_b,
    const int* __restrict__ assign_a, const int* __restrict__ assign_b,
    const float* __restrict__ conv_w,
    const float* __restrict__ g1, const float* __restrict__ b1,
    const float* __restrict__ m1, const float* __restrict__ v1,
    const float* __restrict__ g2, const float* __restrict__ b2,
    const float* __restrict__ m2, const float* __restrict__ v2,
    float* __restrict__ out) {
    __shared__ float s1[CDIM], t1v[CDIM], s2[CDIM], t2v[CDIM];
    __shared__ float faP[CDIM * FPAD];       // 1.7 KB (precompute input)
    __shared__ float fbP[CDIM * FPAD];       // 1.7 KB
    __shared__ float wS[CDIM * WSTR];        // folded W, [o][c], 4.2 KB
    __shared__ float biasS[CDIM];
    __shared__ float pmA[NPAIR * PMS];       // pair-max A, 19.0 KB
    __shared__ float pmB[NPAIR * PMS];       // pair-max B, 19.0 KB
    __shared__ uint32_t pairS[2][TPB];       // packed pair ids, double-buffered

    const int t = threadIdx.x;
    const int lane = t & 31;
    const int wid = t >> 5;                  // 0..3
    const int g = lane >> 2;                 // 0..7
    const int tg = lane & 3;                 // 0..3
    const int b = blockIdx.y;
    const int ptile = blockIdx.x * TILE_P;

    // ---- Setup (once per block) ----
    if (t < CDIM) {
        float sc1 = g1[t] * rsqrtf(v1[t] + EPS_F);
        s1[t] = sc1;
        t1v[t] = b1[t] - m1[t] * sc1;
        float sc2 = g2[t] * rsqrtf(v2[t] + EPS_F);
        s2[t] = sc2;
        t2v[t] = b2[t] - m2[t] * sc2;
    }
    __syncthreads();
    for (int i = t; i < CDIM * CDIM; i += TPB) {
        int o = i >> 5, c = i & 31;
        wS[o * WSTR + c] = conv_w[i] * s1[c] * s2[o];   // [o][c]
    }
    if (t < CDIM) {
        float s = 0.f;
        #pragma unroll
        for (int c = 0; c < CDIM; c++) s += conv_w[t * CDIM + c] * t1v[c];
        biasS[t] = s * s2[t] + t2v[t];
    }
    for (int i = t; i < CDIM * NA; i += TPB) {          // 384 > TPB: strided
        int c = i / NA, j = i - c * NA;
        faP[c * FPAD + j] = feat_a[b * CDIM * NA + i];
    }
    for (int i = t; i < CDIM * NB; i += TPB) {
        int c = i / NB, j = i - c * NB;
        fbP[c * FPAD + j] = feat_b[b * CDIM * NB + i];
    }
    __syncthreads();

    // ---- Pair-max tables: pm[pair][c] = max(f[c][i0], f[c][i1]) ----
    for (int i = t; i < NPAIR * CDIM; i += TPB) {
        int pair = i >> 5, c = i & 31;
        int i0 = pair / 12, i1 = pair - i0 * 12;
        pmA[pair * PMS + c] = fmaxf(faP[c * FPAD + i0], faP[c * FPAD + i1]);
        pmB[pair * PMS + c] = fmaxf(fbP[c * FPAD + i0], fbP[c * FPAD + i1]);
    }

    // ---- A fragments (W tf32 hi/lo), resident for whole kernel (R12/R16) ----
    uint32_t aH[2][4][4], aL[2][4][4];
    #pragma unroll
    for (int mt = 0; mt < 2; mt++) {
        #pragma unroll
        for (int kt = 0; kt < 4; kt++) {
            int r0 = (mt * 16 + g) * WSTR, r1 = (mt * 16 + g + 8) * WSTR;
            int c0 = kt * 8 + tg;
            float w0 = wS[r0 + c0];
            float w1 = wS[r1 + c0];
            float w2 = wS[r0 + c0 + 4];
            float w3 = wS[r1 + c0 + 4];
            aH[mt][kt][0] = to_tf32(w0);
            aH[mt][kt][1] = to_tf32(w1);
            aH[mt][kt][2] = to_tf32(w2);
            aH[mt][kt][3] = to_tf32(w3);
            aL[mt][kt][0] = to_tf32(w0 - __uint_as_float(aH[mt][kt][0]));
            aL[mt][kt][1] = to_tf32(w1 - __uint_as_float(aH[mt][kt][1]));
            aL[mt][kt][2] = to_tf32(w2 - __uint_as_float(aH[mt][kt][2]));
            aL[mt][kt][3] = to_tf32(w3 - __uint_as_float(aH[mt][kt][3]));
        }
    }
    float bias_r[2][2];
    bias_r[0][0] = biasS[g];
    bias_r[0][1] = biasS[g + 8];
    bias_r[1][0] = biasS[16 + g];
    bias_r[1][1] = biasS[24 + g];

    for (int ck = 0; ck < NCHUNK; ck++) {
        const int cbase = ptile + ck * CHUNK;

        // ---- Pair ids for owned points 2t, 2t+1 (one packed word) ----
        {
            const int4 qa = __ldg((const int4*)(assign_a + 4 * (cbase / 2 + t)));
            const int4 qb = __ldg((const int4*)(assign_b + 4 * (cbase / 2 + t)));
            uint32_t pk = (uint32_t)(qa.x * 12 + qa.y) |
                          ((uint32_t)(qb.x * 12 + qb.y) << 8) |
                          ((uint32_t)(qa.z * 12 + qa.w) << 16) |
                          ((uint32_t)(qb.z * 12 + qb.w) << 24);
            pairS[ck & 1][t] = pk;
        }
        __syncthreads();   // pairS visible (pm/setup covered by first pass)

        // ---- mma phase: warp = 32 o x 64 pts, 8 n-tiles; gather fused ----
        const int wpt0 = wid * 64;
        #pragma unroll
        for (int nt = 0; nt < 8; nt++) {
            // this lane's point: ptb = wpt0 + nt*8 + g
            const uint32_t pw = pairS[ck & 1][wid * 32 + nt * 4 + (g >> 1)];
            const uint32_t sh = (g & 1) << 4;
            const float* pA = pmA + ((pw >> sh) & 0xff) * PMS;
            const float* pB = pmB + ((pw >> (sh + 8)) & 0xff) * PMS;

            uint32_t bh[4][2], bl[4][2];
            #pragma unroll
            for (int kt = 0; kt < 4; kt++) {
                const int c0 = kt * 8 + tg;
                float f0 = fmaxf(pA[c0], pB[c0]);
                float f1 = fmaxf(pA[c0 + 4], pB[c0 + 4]);
                bh[kt][0] = to_tf32(f0);
                bh[kt][1] = to_tf32(f1);
                bl[kt][0] = to_tf32(f0 - __uint_as_float(bh[kt][0]));
                bl[kt][1] = to_tf32(f1 - __uint_as_float(bh[kt][1]));
            }

            float d[2][4] = {{0.f, 0.f, 0.f, 0.f}, {0.f, 0.f, 0.f, 0.f}};
            #pragma unroll
            for (int kt = 0; kt < 4; kt++) {
                #pragma unroll
                for (int mt = 0; mt < 2; mt++) {
                    mma_tf32(d[mt][0], d[mt][1], d[mt][2], d[mt][3],
                             aH[mt][kt][0], aH[mt][kt][1], aH[mt][kt][2], aH[mt][kt][3],
                             bh[kt][0], bh[kt][1]);
                    mma_tf32(d[mt][0], d[mt][1], d[mt][2], d[mt][3],
                             aL[mt][kt][0], aL[mt][kt][1], aL[mt][kt][2], aL[mt][kt][3],
                             bh[kt][0], bh[kt][1]);
                    mma_tf32(d[mt][0], d[mt][1], d[mt][2], d[mt][3],
                             aH[mt][kt][0], aH[mt][kt][1], aH[mt][kt][2], aH[mt][kt][3],
                             bl[kt][0], bl[kt][1]);
                }
            }

            // Epilogue: rows o = mt*16+g (+8), cols pt = nt*8 + tg*2 (+1)
            const size_t pcol = (size_t)cbase + wpt0 + nt * 8 + tg * 2;
            float* ob = out + (size_t)b * CDIM * PDIM + pcol;
            #pragma unroll
            for (int mt = 0; mt < 2; mt++) {
                float x0 = fmaxf(d[mt][0] + bias_r[mt][0], 0.f);
                float x1 = fmaxf(d[mt][1] + bias_r[mt][0], 0.f);
                float x2 = fmaxf(d[mt][2] + bias_r[mt][1], 0.f);
                float x3 = fmaxf(d[mt][3] + bias_r[mt][1], 0.f);
                *reinterpret_cast<float2*>(ob + (size_t)(mt * 16 + g) * PDIM) =
                    make_float2(x0, x1);
                *reinterpret_cast<float2*>(ob + (size_t)(mt * 16 + g + 8) * PDIM) =
                    make_float2(x2, x3);
            }
        }
    }
}

// ---------------------------------------------------------------------------
// Launch
// ---------------------------------------------------------------------------
extern "C" void kernel_launch(void* const* d_in, const int* in_sizes, int n_in,
                              void* d_out, int out_size) {
    const float* feat_a = (const float*)d_in[0];
    const float* feat_b = (const float*)d_in[1];
    const int* assign_a = (const int*)d_in[2];
    const int* assign_b = (const int*)d_in[3];
    const float* bn1_gamma = (const float*)d_in[4];
    const float* bn1_beta = (const float*)d_in[5];
    const float* bn1_mean = (const float*)d_in[6];
    const float* bn1_var = (const float*)d_in[7];
    const float* conv_w = (const float*)d_in[8];
    const float* bn2_gamma = (const float*)d_in[9];
    const float* bn2_beta = (const float*)d_in[10];
    const float* bn2_mean = (const float*)d_in[11];
    const float* bn2_var = (const float*)d_in[12];
    float* out = (float*)d_out;

    dim3 grid(PDIM / TILE_P, BDIM);
    feynnet_kernel<<<grid, TPB>>>(feat_a, feat_b, assign_a, assign_b,
                                  conv_w,
                                  bn1_gamma, bn1_beta, bn1_mean, bn1_var,
                                  bn2_gamma, bn2_beta, bn2_mean, bn2_var,
                                  out);
}